// round 12
// baseline (speedup 1.0000x reference)
#include <cuda_runtime.h>
#include <cuda_bf16.h>

#define BB 2048
#define TT 128
#define NN 64
#define HH 128
#define THR 256   // threads per CTA (8 warps)
#define GRID 296  // 2 CTAs per SM
#define NFULL 272 // CTAs with 7 batches; remaining 24 have 6
#define HCP 264   // hc row stride (floats): [b][0:128)=h, [128:256)=c

typedef unsigned long long ull;

// ---------------- device scratch (allocation-free: __device__ globals) -------
__device__ __align__(16) __nv_bfloat16 g_prex_bf[(size_t)BB * NN * HH]; // [b][n][kq]
__device__ __align__(16) uint2 g_WatP[2 * 32 * 128]; // [part][jb][k]: j-quad attn wts bf16
__device__ __align__(16) float g_W1xT[TT * HH];      // [t][k]
__device__ __align__(16) float4 g_WhhJ[64 * 256];    // [jp][tid]: {Wg0j0,Wg0j1,Wg1j0,Wg1j1}
__device__ __align__(16) float4 g_WihJ[32 * 256];    // [np][tid]
__device__ __align__(16) float2 g_bJ[256];           // [tid]: (bias_g0, bias_g1)

__device__ __forceinline__ ull pk2(float a, float b) {
    ull r; asm("mov.b64 %0,{%1,%2};" : "=l"(r) : "f"(a), "f"(b)); return r;
}
__device__ __forceinline__ void fma2(ull& d, ull a, ull b) {
    asm("fma.rn.f32x2 %0, %1, %2, %0;" : "+l"(d) : "l"(a), "l"(b));
}
__device__ __forceinline__ float2 up2(ull v) {
    float2 r; asm("mov.b64 {%0,%1},%2;" : "=f"(r.x), "=f"(r.y) : "l"(v)); return r;
}
// bf16x2 word -> packed f32x2 (low bf16 -> low f32)
__device__ __forceinline__ ull expw(unsigned wd) {
    unsigned lo = wd << 16, hi = wd & 0xFFFF0000u;
    ull r; asm("mov.b64 %0,{%1,%2};" : "=l"(r) : "r"(lo), "r"(hi)); return r;
}
__device__ __forceinline__ float tanh_fast(float x) {
    float y; asm("tanh.approx.f32 %0, %1;" : "=f"(y) : "f"(x)); return y;
}
__device__ __forceinline__ float sigmoid_f(float x) {
    return 1.0f / (1.0f + __expf(-x));
}
__device__ __forceinline__ void fma4(float4& a, float s, const float4 w) {
    a.x = fmaf(s, w.x, a.x); a.y = fmaf(s, w.y, a.y);
    a.z = fmaf(s, w.z, a.z); a.w = fmaf(s, w.w, a.w);
}
__device__ __forceinline__ unsigned b2u(__nv_bfloat162 v) {
    unsigned r; *(__nv_bfloat162*)&r = v; return r;
}

// ---------------- kernel 0: weight layout prep --------------------------------
__global__ void prep_kernel(const float* __restrict__ W_attn1,
                            const float* __restrict__ W_ih,
                            const float* __restrict__ W_hh,
                            const float* __restrict__ b_ih,
                            const float* __restrict__ b_hh)
{
    int tid = blockIdx.x * blockDim.x + threadIdx.x;
    int nt  = gridDim.x * blockDim.x;
    // attention wts: W^T[j][k] = W_attn1[k*384 + j]; part p covers j = p*128..+127
    // WatP[p][jb][k] = { bf16x2(j0,j1; k), bf16x2(j2,j3; k) }, j0 = p*128 + jb*4
    for (int i = tid; i < 2 * 32 * 128; i += nt) {
        int p = i >> 12, jb = (i >> 7) & 31, k = i & 127;
        int j0 = p * 128 + jb * 4;
        uint2 v;
        v.x = b2u(__floats2bfloat162_rn(W_attn1[k*384 + j0],     W_attn1[k*384 + j0 + 1]));
        v.y = b2u(__floats2bfloat162_rn(W_attn1[k*384 + j0 + 2], W_attn1[k*384 + j0 + 3]));
        g_WatP[i] = v;
    }
    for (int i = tid; i < TT * HH; i += nt) {
        int t = i >> 7, k = i & 127;
        g_W1xT[i] = W_attn1[k * 384 + 256 + t];
    }
    // gate weights, j-pair interleaved per thread (q = tt>>1, gates 2gp,2gp+1)
    for (int i = tid; i < 64 * 256; i += nt) {
        int jp = i >> 8, tt = i & 255;
        int q = tt >> 1, gp = tt & 1, g0 = gp * 2, g1 = g0 + 1;
        int j0 = jp * 2, j1 = j0 + 1;
        float4 v;
        v.x = W_hh[(g0 * HH + q) * HH + j0];
        v.y = W_hh[(g0 * HH + q) * HH + j1];
        v.z = W_hh[(g1 * HH + q) * HH + j0];
        v.w = W_hh[(g1 * HH + q) * HH + j1];
        g_WhhJ[i] = v;
    }
    for (int i = tid; i < 32 * 256; i += nt) {
        int np = i >> 8, tt = i & 255;
        int q = tt >> 1, gp = tt & 1, g0 = gp * 2, g1 = g0 + 1;
        int n0 = np * 2, n1 = n0 + 1;
        float4 v;
        v.x = W_ih[(g0 * HH + q) * NN + n0];
        v.y = W_ih[(g0 * HH + q) * NN + n1];
        v.z = W_ih[(g1 * HH + q) * NN + n0];
        v.w = W_ih[(g1 * HH + q) * NN + n1];
        g_WihJ[i] = v;
    }
    for (int i = tid; i < 256; i += nt) {
        int q = i >> 1, gp = i & 1, g0 = gp * 2, g1 = g0 + 1;
        float2 v;
        v.x = b_ih[g0 * HH + q] + b_hh[g0 * HH + q];
        v.y = b_ih[g1 * HH + q] + b_hh[g1 * HH + q];
        g_bJ[i] = v;
    }
}

// ---------------- kernel 1: pre_x (bf16 out) ----------------------------------
__global__ __launch_bounds__(256) void prex_kernel(const float* __restrict__ X,
                                                   const float* __restrict__ b_attn1)
{
    __shared__ float sX[TT * NN];
    int b = blockIdx.x;
    int tid = threadIdx.x;
    const float* Xb = X + (size_t)b * TT * NN;
    for (int i = tid; i < TT * NN; i += 256) sX[i] = Xb[i];
    __syncthreads();

    const float4* W4  = (const float4*)g_W1xT;
    const float4* b14 = (const float4*)b_attn1;
    uint2* out2 = (uint2*)(g_prex_bf + (size_t)b * NN * HH);

    for (int qi = tid; qi < NN * 32; qi += 256) {
        int n = qi >> 5, kq = qi & 31;
        float4 acc = b14[kq];
        #pragma unroll 4
        for (int t = 0; t < TT; ++t) {
            float x = sX[t * NN + n];
            fma4(acc, x, W4[t * 32 + kq]);
        }
        uint2 st;
        st.x = b2u(__floats2bfloat162_rn(acc.x, acc.y));
        st.y = b2u(__floats2bfloat162_rn(acc.z, acc.w));
        out2[n * 32 + kq] = st;
    }
}

// dummy: shifts launch numbering so ncu (-s 5 -c 1) lands on rnn_kernel
__global__ void dummy_kernel() {}

// ---------------- kernel 2: the recurrence ------------------------------------
__global__ __launch_bounds__(THR, 2) void rnn_kernel(
    const float* __restrict__ X,
    const float* __restrict__ w_attn2,
    const float* __restrict__ b_attn2,
    float* __restrict__ out)
{
    __shared__ __align__(16) float hc[7 * HCP];      // [b]: h [0:128), c [128:256)
    __shared__ __align__(16) float sUh[2 * 7 * 128]; // [part][b][k] u partials
    __shared__ __align__(16) float sXT[7 * 64];      // [b][n] x_tilde

    int tid = threadIdx.x;
    int l = tid & 31;
    int w = tid >> 5;                      // warp 0..7
    int part = tid >> 7;                   // 0: attn-h half, 1: attn-c half
    int katt = tid & 127;                  // attention k owned by this thread
    int cta = blockIdx.x;
    int cnt = (cta < NFULL) ? 7 : 6;
    size_t b0 = (cta < NFULL) ? (size_t)cta * 7
                              : (size_t)(NFULL * 7 + (cta - NFULL) * 6);

    for (int i = tid; i < 7 * HCP; i += THR) hc[i] = 0.0f;
    for (int i = tid; i < 7 * 64; i += THR) sXT[i] = 0.0f;

    float b2 = b_attn2[0];
    float4 w2v = ((const float4*)w_attn2)[l];   // k-quad l for (b)

    // (d)/(e) mapping
    int qe = tid >> 1, gp = tid & 1;
    float2 bj = g_bJ[tid];
    const ulonglong2* Wh = (const ulonglong2*)g_WhhJ + tid;
    const ulonglong2* Wi = (const ulonglong2*)g_WihJ + tid;
    const uint2* Wat = g_WatP + part * 4096 + katt;   // [jb][128]

    // (b) pre_x / X pointers for the warp's batch
    int mw = (w < cnt) ? w : cnt - 1;
    const uint2* prb = (const uint2*)g_prex_bf + (size_t)(b0 + mw) * 2048;
    const float* Xw = X + (size_t)(b0 + mw) * TT * NN;

    __syncthreads();

    for (int t = 0; t < TT; ++t) {
        // ---- (A) fused: gate-h GEMM + attention-u GEMM (share h broadcast LDS)
        ull gA0[7], gA1[7], uA[7];
        #pragma unroll
        for (int b = 0; b < 7; ++b) { gA0[b] = 0ull; gA1[b] = 0ull; uA[b] = 0ull; }
        #pragma unroll 2
        for (int jb = 0; jb < 32; ++jb) {
            ulonglong2 wa = Wh[(size_t)(2 * jb) * 256];
            ulonglong2 wb = Wh[(size_t)(2 * jb + 1) * 256];
            uint2 aw = Wat[jb * 128];
            ull awx = expw(aw.x), awy = expw(aw.y);
            if (part == 0) {
                #pragma unroll
                for (int b = 0; b < 7; ++b) {
                    ulonglong2 hp = *(const ulonglong2*)(hc + b * HCP + jb * 4);
                    fma2(gA0[b], hp.x, wa.x); fma2(gA1[b], hp.x, wa.y);
                    fma2(gA0[b], hp.y, wb.x); fma2(gA1[b], hp.y, wb.y);
                    fma2(uA[b], hp.x, awx);   fma2(uA[b], hp.y, awy);
                }
            } else {
                #pragma unroll
                for (int b = 0; b < 7; ++b) {
                    ulonglong2 hp = *(const ulonglong2*)(hc + b * HCP + jb * 4);
                    ulonglong2 cp = *(const ulonglong2*)(hc + b * HCP + 128 + jb * 4);
                    fma2(gA0[b], hp.x, wa.x); fma2(gA1[b], hp.x, wa.y);
                    fma2(gA0[b], hp.y, wb.x); fma2(gA1[b], hp.y, wb.y);
                    fma2(uA[b], cp.x, awx);   fma2(uA[b], cp.y, awy);
                }
            }
        }
        // u partials -> smem (frees uA regs before (b))
        #pragma unroll
        for (int b = 0; b < 7; ++b) {
            float2 r = up2(uA[b]);
            sUh[(part * 7 + b) * 128 + katt] = r.x + r.y;
        }
        __syncthreads();

        // ---- (b) attention tanh + scores + softmax + x_tilde (warp = batch)
        if (w < cnt) {
            int kq = l & 7;
            const float4* ua = (const float4*)(sUh + w * 128);
            const float4* ub = (const float4*)(sUh + (7 + w) * 128);
            float4 u0, u1, u2, u3;
            {
                float4 a0 = ua[kq],      b0_ = ub[kq];
                float4 a1 = ua[kq + 8],  b1_ = ub[kq + 8];
                float4 a2 = ua[kq + 16], b2_ = ub[kq + 16];
                float4 a3 = ua[kq + 24], b3_ = ub[kq + 24];
                u0 = make_float4(a0.x + b0_.x, a0.y + b0_.y, a0.z + b0_.z, a0.w + b0_.w);
                u1 = make_float4(a1.x + b1_.x, a1.y + b1_.y, a1.z + b1_.z, a1.w + b1_.w);
                u2 = make_float4(a2.x + b2_.x, a2.y + b2_.y, a2.z + b2_.z, a2.w + b2_.w);
                u3 = make_float4(a3.x + b3_.x, a3.y + b3_.y, a3.z + b3_.z, a3.w + b3_.w);
            }
            const float4* w24 = (const float4*)w_attn2;
            float4 wA = w24[kq], wB = w24[kq + 8], wC = w24[kq + 16], wD = w24[kq + 24];
            float ee[2];
            #pragma unroll
            for (int p = 0; p < 2; ++p) {
                int nb = p * 32 + (l & 24);
                const uint2* pp = prb + (size_t)nb * 32 + kq;
                uint2 c0 = __ldcs(pp), c1 = __ldcs(pp + 8);
                uint2 c2 = __ldcs(pp + 16), c3 = __ldcs(pp + 24);
                float v[8];
                #pragma unroll
                for (int i = 0; i < 8; ++i) {
                    const uint2* pn = prb + (size_t)(nb + ((i + 1) & 7)) * 32 + kq;
                    uint2 n0 = __ldcs(pn), n1 = __ldcs(pn + 8);
                    uint2 n2 = __ldcs(pn + 16), n3 = __ldcs(pn + 24);
                    float s;
                    {
                        float2 a01 = __bfloat1622float2(*(const __nv_bfloat162*)&c0.x);
                        float2 a23 = __bfloat1622float2(*(const __nv_bfloat162*)&c0.y);
                        s = tanh_fast(a01.x + u0.x) * wA.x;
                        s = fmaf(tanh_fast(a01.y + u0.y), wA.y, s);
                        s = fmaf(tanh_fast(a23.x + u0.z), wA.z, s);
                        s = fmaf(tanh_fast(a23.y + u0.w), wA.w, s);
                    }
                    {
                        float2 a01 = __bfloat1622float2(*(const __nv_bfloat162*)&c1.x);
                        float2 a23 = __bfloat1622float2(*(const __nv_bfloat162*)&c1.y);
                        s = fmaf(tanh_fast(a01.x + u1.x), wB.x, s);
                        s = fmaf(tanh_fast(a01.y + u1.y), wB.y, s);
                        s = fmaf(tanh_fast(a23.x + u1.z), wB.z, s);
                        s = fmaf(tanh_fast(a23.y + u1.w), wB.w, s);
                    }
                    {
                        float2 a01 = __bfloat1622float2(*(const __nv_bfloat162*)&c2.x);
                        float2 a23 = __bfloat1622float2(*(const __nv_bfloat162*)&c2.y);
                        s = fmaf(tanh_fast(a01.x + u2.x), wC.x, s);
                        s = fmaf(tanh_fast(a01.y + u2.y), wC.y, s);
                        s = fmaf(tanh_fast(a23.x + u2.z), wC.z, s);
                        s = fmaf(tanh_fast(a23.y + u2.w), wC.w, s);
                    }
                    {
                        float2 a01 = __bfloat1622float2(*(const __nv_bfloat162*)&c3.x);
                        float2 a23 = __bfloat1622float2(*(const __nv_bfloat162*)&c3.y);
                        s = fmaf(tanh_fast(a01.x + u3.x), wD.x, s);
                        s = fmaf(tanh_fast(a01.y + u3.y), wD.y, s);
                        s = fmaf(tanh_fast(a23.x + u3.z), wD.z, s);
                        s = fmaf(tanh_fast(a23.y + u3.w), wD.w, s);
                    }
                    v[i] = s;
                    c0 = n0; c1 = n1; c2 = n2; c3 = n3;
                }
                bool h1 = l & 1, h2 = l & 2, h4 = l & 4;
                float s0 = h1 ? v[0] : v[1];
                float a0 = (h1 ? v[1] : v[0]) + __shfl_xor_sync(0xffffffffu, s0, 1);
                float s1 = h1 ? v[2] : v[3];
                float a1 = (h1 ? v[3] : v[2]) + __shfl_xor_sync(0xffffffffu, s1, 1);
                float s2 = h1 ? v[4] : v[5];
                float a2 = (h1 ? v[5] : v[4]) + __shfl_xor_sync(0xffffffffu, s2, 1);
                float s3 = h1 ? v[6] : v[7];
                float a3 = (h1 ? v[7] : v[6]) + __shfl_xor_sync(0xffffffffu, s3, 1);
                float t0 = h2 ? a0 : a1;
                float bb0 = (h2 ? a1 : a0) + __shfl_xor_sync(0xffffffffu, t0, 2);
                float t1 = h2 ? a2 : a3;
                float bb1 = (h2 ? a3 : a2) + __shfl_xor_sync(0xffffffffu, t1, 2);
                float t2 = h4 ? bb0 : bb1;
                float ev = (h4 ? bb1 : bb0) + __shfl_xor_sync(0xffffffffu, t2, 4);
                ee[p] = ev + b2;
            }
            float e0 = ee[0], e1 = ee[1];
            float mx = fmaxf(e0, e1);
            #pragma unroll
            for (int o = 16; o > 0; o >>= 1)
                mx = fmaxf(mx, __shfl_xor_sync(0xffffffffu, mx, o));
            float x0 = __expf(e0 - mx), x1 = __expf(e1 - mx);
            float sm = x0 + x1;
            #pragma unroll
            for (int o = 16; o > 0; o >>= 1)
                sm += __shfl_xor_sync(0xffffffffu, sm, o);
            float inv = 1.0f / sm;
            const float* Xr = Xw + (size_t)t * NN;
            sXT[w * 64 + l]      = x0 * inv * Xr[l];
            sXT[w * 64 + l + 32] = x1 * inv * Xr[l + 32];
        }
        __syncthreads();

        // ---- (d2) Wih . x_tilde
        {
            #pragma unroll 2
            for (int nb4 = 0; nb4 < 16; ++nb4) {
                ulonglong2 wa = Wi[(size_t)(2 * nb4) * 256];
                ulonglong2 wb = Wi[(size_t)(2 * nb4 + 1) * 256];
                #pragma unroll
                for (int b = 0; b < 7; ++b) {
                    ulonglong2 xp = *(const ulonglong2*)(sXT + b * 64 + nb4 * 4);
                    fma2(gA0[b], xp.x, wa.x);
                    fma2(gA1[b], xp.x, wa.y);
                    fma2(gA0[b], xp.y, wb.x);
                    fma2(gA1[b], xp.y, wb.y);
                }
            }
        }

        // ---- (e) horizontal sum + gate exchange (lane^1) + LSTM update
        {
            float s0[7], s1[7], p0[7], p1[7];
            #pragma unroll
            for (int b = 0; b < 7; ++b) {
                float2 r0 = up2(gA0[b]), r1 = up2(gA1[b]);
                s0[b] = r0.x + r0.y + bj.x;
                s1[b] = r1.x + r1.y + bj.y;
            }
            #pragma unroll
            for (int b = 0; b < 7; ++b) {
                p0[b] = __shfl_xor_sync(0xffffffffu, s0[b], 1);
                p1[b] = __shfl_xor_sync(0xffffffffu, s1[b], 1);
            }
            // gp=0 lane owns (i,f) & batches 0..3; gp=1 owns (g,o) & batches 4..6
            #pragma unroll
            for (int b = 0; b < 7; ++b) {
                bool mine = gp ? (b >= 4) : (b < 4);
                if (mine) {
                    float gi = gp ? p0[b] : s0[b];
                    float gf = gp ? p1[b] : s1[b];
                    float gg = gp ? s0[b] : p0[b];
                    float go = gp ? s1[b] : p1[b];
                    float iv = sigmoid_f(gi);
                    float fv = sigmoid_f(gf);
                    float gv = tanhf(gg);
                    float ov = sigmoid_f(go);
                    float cold = hc[b * HCP + 128 + qe];
                    float c2 = fv * cold + iv * gv;
                    float hn = ov * tanhf(c2);
                    hc[b * HCP + qe]       = hn;
                    hc[b * HCP + 128 + qe] = c2;
                    if (b < cnt)
                        out[((size_t)(b0 + b) * TT + t) * HH + qe] = hn;
                }
            }
        }
        __syncthreads();
    }
}

// ---------------- launch ------------------------------------------------------
extern "C" void kernel_launch(void* const* d_in, const int* in_sizes, int n_in,
                              void* d_out, int out_size) {
    const float* X       = (const float*)d_in[0];
    const float* W_attn1 = (const float*)d_in[1];
    const float* b_attn1 = (const float*)d_in[2];
    const float* w_attn2 = (const float*)d_in[3];
    const float* b_attn2 = (const float*)d_in[4];
    const float* W_ih    = (const float*)d_in[5];
    const float* W_hh    = (const float*)d_in[6];
    const float* b_ih    = (const float*)d_in[7];
    const float* b_hh    = (const float*)d_in[8];
    float* out = (float*)d_out;

    prep_kernel<<<64, 256>>>(W_attn1, W_ih, W_hh, b_ih, b_hh);
    prex_kernel<<<BB, 256>>>(X, b_attn1);
    dummy_kernel<<<1, 32>>>();   // aligns ncu -s 5 -c 1 onto rnn_kernel
    rnn_kernel<<<GRID, THR>>>(X, w_attn2, b_attn2, out);
}

// round 13
// speedup vs baseline: 1.0335x; 1.0335x over previous
#include <cuda_runtime.h>
#include <cuda_bf16.h>

#define BB 2048
#define TT 128
#define NN 64
#define HH 128
#define THR 256   // 8 warps: 0-3 ATTN, 4-7 GATE
#define GRID 296  // 2 CTAs/SM
#define NFULL 272 // 272 CTAs x 7 batches + 24 x 6 = 2048

typedef unsigned long long ull;

// ---------------- device scratch -----------------------------------------
__device__ __align__(16) __nv_bfloat16 g_prex_bf[(size_t)BB * NN * HH]; // [b][n][kq]
__device__ __align__(16) uint2  g_WatJ[128 * 64];   // [jp][kp] attn wts bf16 pairs
__device__ __align__(16) float  g_W1xT[TT * HH];    // [t][k]
__device__ __align__(16) float4 g_WhhQ[128 * 128];  // [j][q] = (Wi,Wf,Wg,Wo)
__device__ __align__(16) float4 g_WihQ[64 * 128];   // [n][q]
__device__ __align__(16) float4 g_bQ[128];          // [q] bias (i,f,g,o)

__device__ __forceinline__ ull pk2(float a, float b) {
    ull r; asm("mov.b64 %0,{%1,%2};" : "=l"(r) : "f"(a), "f"(b)); return r;
}
__device__ __forceinline__ void fma2(ull& d, ull a, ull b) {
    asm("fma.rn.f32x2 %0, %1, %2, %0;" : "+l"(d) : "l"(a), "l"(b));
}
__device__ __forceinline__ float2 up2(ull v) {
    float2 r; asm("mov.b64 {%0,%1},%2;" : "=f"(r.x), "=f"(r.y) : "l"(v)); return r;
}
__device__ __forceinline__ ull expw(unsigned wd) {   // bf16x2 -> f32x2
    unsigned lo = wd << 16, hi = wd & 0xFFFF0000u;
    ull r; asm("mov.b64 %0,{%1,%2};" : "=l"(r) : "r"(lo), "r"(hi)); return r;
}
__device__ __forceinline__ float tanh_fast(float x) {
    float y; asm("tanh.approx.f32 %0, %1;" : "=f"(y) : "f"(x)); return y;
}
__device__ __forceinline__ float sigmoid_f(float x) {
    return 1.0f / (1.0f + __expf(-x));
}
__device__ __forceinline__ void fma4(float4& a, float s, const float4 w) {
    a.x = fmaf(s, w.x, a.x); a.y = fmaf(s, w.y, a.y);
    a.z = fmaf(s, w.z, a.z); a.w = fmaf(s, w.w, a.w);
}
__device__ __forceinline__ unsigned b2u(__nv_bfloat162 v) {
    unsigned r; *(__nv_bfloat162*)&r = v; return r;
}

// ---------------- kernel 0: weight layout prep ----------------------------
__global__ void prep_kernel(const float* __restrict__ W_attn1,
                            const float* __restrict__ W_ih,
                            const float* __restrict__ W_hh,
                            const float* __restrict__ b_ih,
                            const float* __restrict__ b_hh)
{
    int tid = blockIdx.x * blockDim.x + threadIdx.x;
    int nt  = gridDim.x * blockDim.x;
    // Wt[j][k] = W_attn1[k*384 + j], j<128: W1_h col, j in [128,256): W1_s col
    for (int i = tid; i < 128 * 64; i += nt) {
        int jp = i >> 6, kp = i & 63;
        int j0 = jp * 2, j1 = j0 + 1, k0 = kp * 2, k1 = k0 + 1;
        uint2 v;
        v.x = b2u(__floats2bfloat162_rn(W_attn1[k0*384 + j0], W_attn1[k1*384 + j0]));
        v.y = b2u(__floats2bfloat162_rn(W_attn1[k0*384 + j1], W_attn1[k1*384 + j1]));
        g_WatJ[i] = v;
    }
    for (int i = tid; i < TT * HH; i += nt) {
        int t = i >> 7, k = i & 127;
        g_W1xT[i] = W_attn1[k * 384 + 256 + t];
    }
    for (int i = tid; i < 128 * 128; i += nt) {
        int j = i >> 7, q = i & 127;
        float4 v;
        v.x = W_hh[(0*HH + q)*HH + j]; v.y = W_hh[(1*HH + q)*HH + j];
        v.z = W_hh[(2*HH + q)*HH + j]; v.w = W_hh[(3*HH + q)*HH + j];
        g_WhhQ[i] = v;
    }
    for (int i = tid; i < 64 * 128; i += nt) {
        int n = i >> 7, q = i & 127;
        float4 v;
        v.x = W_ih[(0*HH + q)*NN + n]; v.y = W_ih[(1*HH + q)*NN + n];
        v.z = W_ih[(2*HH + q)*NN + n]; v.w = W_ih[(3*HH + q)*NN + n];
        g_WihQ[i] = v;
    }
    for (int i = tid; i < 128; i += nt) {
        float4 v;
        v.x = b_ih[0*HH + i] + b_hh[0*HH + i];
        v.y = b_ih[1*HH + i] + b_hh[1*HH + i];
        v.z = b_ih[2*HH + i] + b_hh[2*HH + i];
        v.w = b_ih[3*HH + i] + b_hh[3*HH + i];
        g_bQ[i] = v;
    }
}

// ---------------- kernel 1: pre_x (bf16 out) ------------------------------
__global__ __launch_bounds__(256) void prex_kernel(const float* __restrict__ X,
                                                   const float* __restrict__ b_attn1)
{
    __shared__ float sX[TT * NN];
    int b = blockIdx.x;
    int tid = threadIdx.x;
    const float* Xb = X + (size_t)b * TT * NN;
    for (int i = tid; i < TT * NN; i += 256) sX[i] = Xb[i];
    __syncthreads();

    const float4* W4  = (const float4*)g_W1xT;
    const float4* b14 = (const float4*)b_attn1;
    uint2* out2 = (uint2*)(g_prex_bf + (size_t)b * NN * HH);

    for (int qi = tid; qi < NN * 32; qi += 256) {
        int n = qi >> 5, kq = qi & 31;
        float4 acc = b14[kq];
        #pragma unroll 4
        for (int t = 0; t < TT; ++t) {
            float x = sX[t * NN + n];
            fma4(acc, x, W4[t * 32 + kq]);
        }
        uint2 st;
        st.x = b2u(__floats2bfloat162_rn(acc.x, acc.y));
        st.y = b2u(__floats2bfloat162_rn(acc.z, acc.w));
        out2[n * 32 + kq] = st;
    }
}

// dummy: aligns ncu -s 5 -c 1 onto rnn_kernel
__global__ void dummy_kernel() {}

// ---------------- attention tanh/softmax for one batch --------------------
__device__ __forceinline__ void attn_batch(
    int b, int l, int kqd, const ull* sUp, const uint2* prb, const float* Xr,
    float4 wA, float4 wB, float4 wC, float4 wD, float b2, ull* xw)
{
    // assemble u quads = part0 + part1 partials
    const ulonglong2* u0p = (const ulonglong2*)(sUp + b * 66);
    const ulonglong2* u1p = (const ulonglong2*)(sUp + (7 + b) * 66);
    float4 u0, u1, u2, u3;
    {
        ulonglong2 a = u0p[kqd], c = u1p[kqd];
        float2 ax = up2(a.x), ay = up2(a.y), cx = up2(c.x), cy = up2(c.y);
        u0 = make_float4(ax.x + cx.x, ax.y + cx.y, ay.x + cy.x, ay.y + cy.y);
        a = u0p[kqd + 8];  c = u1p[kqd + 8];
        ax = up2(a.x); ay = up2(a.y); cx = up2(c.x); cy = up2(c.y);
        u1 = make_float4(ax.x + cx.x, ax.y + cx.y, ay.x + cy.x, ay.y + cy.y);
        a = u0p[kqd + 16]; c = u1p[kqd + 16];
        ax = up2(a.x); ay = up2(a.y); cx = up2(c.x); cy = up2(c.y);
        u2 = make_float4(ax.x + cx.x, ax.y + cx.y, ay.x + cy.x, ay.y + cy.y);
        a = u0p[kqd + 24]; c = u1p[kqd + 24];
        ax = up2(a.x); ay = up2(a.y); cx = up2(c.x); cy = up2(c.y);
        u3 = make_float4(ax.x + cx.x, ax.y + cx.y, ay.x + cy.x, ay.y + cy.y);
    }
    float ee[2];
    #pragma unroll
    for (int p = 0; p < 2; ++p) {
        int nb = p * 32 + (l & 24);
        const uint2* pp = prb + (size_t)nb * 32 + kqd;
        uint2 c0 = __ldcs(pp), c1 = __ldcs(pp + 8);
        uint2 c2 = __ldcs(pp + 16), c3 = __ldcs(pp + 24);
        float v[8];
        #pragma unroll
        for (int i = 0; i < 8; ++i) {
            const uint2* pn = prb + (size_t)(nb + ((i + 1) & 7)) * 32 + kqd;
            uint2 n0 = __ldcs(pn), n1 = __ldcs(pn + 8);
            uint2 n2 = __ldcs(pn + 16), n3 = __ldcs(pn + 24);
            float s;
            {
                float2 a01 = __bfloat1622float2(*(const __nv_bfloat162*)&c0.x);
                float2 a23 = __bfloat1622float2(*(const __nv_bfloat162*)&c0.y);
                s = tanh_fast(a01.x + u0.x) * wA.x;
                s = fmaf(tanh_fast(a01.y + u0.y), wA.y, s);
                s = fmaf(tanh_fast(a23.x + u0.z), wA.z, s);
                s = fmaf(tanh_fast(a23.y + u0.w), wA.w, s);
            }
            {
                float2 a01 = __bfloat1622float2(*(const __nv_bfloat162*)&c1.x);
                float2 a23 = __bfloat1622float2(*(const __nv_bfloat162*)&c1.y);
                s = fmaf(tanh_fast(a01.x + u1.x), wB.x, s);
                s = fmaf(tanh_fast(a01.y + u1.y), wB.y, s);
                s = fmaf(tanh_fast(a23.x + u1.z), wB.z, s);
                s = fmaf(tanh_fast(a23.y + u1.w), wB.w, s);
            }
            {
                float2 a01 = __bfloat1622float2(*(const __nv_bfloat162*)&c2.x);
                float2 a23 = __bfloat1622float2(*(const __nv_bfloat162*)&c2.y);
                s = fmaf(tanh_fast(a01.x + u2.x), wC.x, s);
                s = fmaf(tanh_fast(a01.y + u2.y), wC.y, s);
                s = fmaf(tanh_fast(a23.x + u2.z), wC.z, s);
                s = fmaf(tanh_fast(a23.y + u2.w), wC.w, s);
            }
            {
                float2 a01 = __bfloat1622float2(*(const __nv_bfloat162*)&c3.x);
                float2 a23 = __bfloat1622float2(*(const __nv_bfloat162*)&c3.y);
                s = fmaf(tanh_fast(a01.x + u3.x), wD.x, s);
                s = fmaf(tanh_fast(a01.y + u3.y), wD.y, s);
                s = fmaf(tanh_fast(a23.x + u3.z), wD.z, s);
                s = fmaf(tanh_fast(a23.y + u3.w), wD.w, s);
            }
            v[i] = s;
            c0 = n0; c1 = n1; c2 = n2; c3 = n3;
        }
        bool h1 = l & 1, h2 = l & 2, h4 = l & 4;
        float s0 = h1 ? v[0] : v[1];
        float a0 = (h1 ? v[1] : v[0]) + __shfl_xor_sync(0xffffffffu, s0, 1);
        float s1 = h1 ? v[2] : v[3];
        float a1 = (h1 ? v[3] : v[2]) + __shfl_xor_sync(0xffffffffu, s1, 1);
        float s2 = h1 ? v[4] : v[5];
        float a2 = (h1 ? v[5] : v[4]) + __shfl_xor_sync(0xffffffffu, s2, 1);
        float s3 = h1 ? v[6] : v[7];
        float a3 = (h1 ? v[7] : v[6]) + __shfl_xor_sync(0xffffffffu, s3, 1);
        float t0 = h2 ? a0 : a1;
        float bb0 = (h2 ? a1 : a0) + __shfl_xor_sync(0xffffffffu, t0, 2);
        float t1 = h2 ? a2 : a3;
        float bb1 = (h2 ? a3 : a2) + __shfl_xor_sync(0xffffffffu, t1, 2);
        float t2 = h4 ? bb0 : bb1;
        float ev = (h4 ? bb1 : bb0) + __shfl_xor_sync(0xffffffffu, t2, 4);
        ee[p] = ev + b2;
    }
    float e0 = ee[0], e1 = ee[1];
    float mx = fmaxf(e0, e1);
    #pragma unroll
    for (int o = 16; o > 0; o >>= 1)
        mx = fmaxf(mx, __shfl_xor_sync(0xffffffffu, mx, o));
    float x0 = __expf(e0 - mx), x1 = __expf(e1 - mx);
    float sm = x0 + x1;
    #pragma unroll
    for (int o = 16; o > 0; o >>= 1)
        sm += __shfl_xor_sync(0xffffffffu, sm, o);
    float inv = 1.0f / sm;
    float xv0 = x0 * inv * Xr[l];
    float xv1 = x1 * inv * Xr[l + 32];
    xw[((l >> 1) * 9 + b) * 2 + (l & 1)]        = pk2(xv0, xv0);
    xw[(((l >> 1) + 16) * 9 + b) * 2 + (l & 1)] = pk2(xv1, xv1);
}

// ---------------- kernel 2: warp-specialized recurrence -------------------
// dyn smem: sWat 65536 | hcdup 18432 (128x9 ull2) | sUp 7392 (2*7*66 ull) | xdup 4608
#define SM_BYTES 95968

__global__ __launch_bounds__(THR, 2) void rnn_kernel(
    const float* __restrict__ X,
    const float* __restrict__ w_attn2,
    const float* __restrict__ b_attn2,
    float* __restrict__ out)
{
    extern __shared__ __align__(16) unsigned char sm[];
    uint2*      sWat  = (uint2*)sm;                    // [128 jp][64 kp]
    ulonglong2* hcdup = (ulonglong2*)(sm + 65536);     // [128 jp][9 b] (jp<64 h, >=64 c)
    ull*        sUp   = (ull*)(sm + 83968);            // [2 part][7 b][66 kp]
    ull*        xw    = (ull*)(sm + 91360);            // xdup [32 np][9 b] ull2 as ulls

    int tid = threadIdx.x, l = tid & 31, w = tid >> 5;
    int cta = blockIdx.x;
    int cnt = (cta < NFULL) ? 7 : 6;
    size_t b0 = (cta < NFULL) ? (size_t)cta * 7
                              : (size_t)(NFULL * 7 + (cta - NFULL) * 6);

    {   // stage attn weights; zero state region
        const uint4* src = (const uint4*)g_WatJ;
        uint4* dst = (uint4*)sWat;
        #pragma unroll 4
        for (int i = tid; i < 4096; i += THR) dst[i] = src[i];
        ull* z = (ull*)(sm + 65536);
        for (int i = tid; i < 3804; i += THR) z[i] = 0ull;
    }
    __syncthreads();

    if (w < 4) {
        // ================= ATTN warps =================
        int part = tid >> 6, kp = tid & 63;
        const uint2* Wrow = sWat + (part * 64) * 64 + kp;
        const ulonglong2* hd = hcdup + (size_t)part * 64 * 9;
        float b2 = b_attn2[0];
        int kqd = l & 7;
        const float4* w24 = (const float4*)w_attn2;
        float4 wA = w24[kqd], wB = w24[kqd + 8], wC = w24[kqd + 16], wD = w24[kqd + 24];
        int mb1 = w + 4;                       // second batch (may be 7 -> skip)
        int cb1 = (mb1 < cnt) ? mb1 : (cnt - 1);
        const uint2* pr0 = (const uint2*)g_prex_bf + (size_t)(b0 + w) * 2048;
        const uint2* pr1 = (const uint2*)g_prex_bf + (size_t)(b0 + cb1) * 2048;
        const float* X0 = X + (size_t)(b0 + w) * TT * NN;
        const float* X1 = X + (size_t)(b0 + cb1) * TT * NN;

        for (int t = 0; t < TT; ++t) {
            // u partials over this part's 128 j (h for part0, c for part1)
            ull a0 = 0, a1 = 0, a2 = 0, a3 = 0, a4 = 0, a5 = 0, a6 = 0;
            #pragma unroll 2
            for (int jp = 0; jp < 64; ++jp) {
                uint2 wt = Wrow[jp * 64];
                ull w0 = expw(wt.x), w1 = expw(wt.y);
                const ulonglong2* h9 = hd + jp * 9;
                ulonglong2 p0 = h9[0], p1 = h9[1], p2 = h9[2], p3 = h9[3];
                ulonglong2 p4 = h9[4], p5 = h9[5], p6 = h9[6];
                fma2(a0, p0.x, w0); fma2(a0, p0.y, w1);
                fma2(a1, p1.x, w0); fma2(a1, p1.y, w1);
                fma2(a2, p2.x, w0); fma2(a2, p2.y, w1);
                fma2(a3, p3.x, w0); fma2(a3, p3.y, w1);
                fma2(a4, p4.x, w0); fma2(a4, p4.y, w1);
                fma2(a5, p5.x, w0); fma2(a5, p5.y, w1);
                fma2(a6, p6.x, w0); fma2(a6, p6.y, w1);
            }
            ull* su = sUp + (size_t)part * 7 * 66 + kp;
            su[0*66] = a0; su[1*66] = a1; su[2*66] = a2; su[3*66] = a3;
            su[4*66] = a4; su[5*66] = a5; su[6*66] = a6;
            asm volatile("bar.sync 3, 128;" ::: "memory");

            attn_batch(w, l, kqd, sUp, pr0, X0 + (size_t)t * NN,
                       wA, wB, wC, wD, b2, xw);
            if (mb1 < 7)
                attn_batch(mb1, l, kqd, sUp, pr1, X1 + (size_t)t * NN,
                           wA, wB, wC, wD, b2, xw);

            asm volatile("bar.sync 1, 256;" ::: "memory");  // x~ ready
            asm volatile("bar.sync 2, 256;" ::: "memory");  // h ready (gate update)
        }
    } else {
        // ================= GATE warps =================
        int q = tid & 127;
        const ulonglong2* Wq  = (const ulonglong2*)g_WhhQ + q;
        const ulonglong2* WqI = (const ulonglong2*)g_WihQ + q;
        float4 bq = g_bQ[q];
        ull bIF = pk2(bq.x, bq.y), bGO = pk2(bq.z, bq.w);
        float cr[7];
        #pragma unroll
        for (int b = 0; b < 7; ++b) cr[b] = 0.0f;
        int qh = (q >> 1) * 9, qc = (64 + (q >> 1)) * 9, qo = (q & 1);
        ull* hw = (ull*)hcdup;

        for (int t = 0; t < TT; ++t) {
            ull aIF[7], aGO[7];
            #pragma unroll
            for (int b = 0; b < 7; ++b) { aIF[b] = bIF; aGO[b] = bGO; }
            // Whh . h (overlaps ATTN's u/tanh/softmax)
            #pragma unroll 2
            for (int jp = 0; jp < 64; ++jp) {
                ulonglong2 w0 = Wq[(size_t)(2 * jp) * 128];
                ulonglong2 w1 = Wq[(size_t)(2 * jp + 1) * 128];
                const ulonglong2* h9 = hcdup + jp * 9;
                #pragma unroll
                for (int b = 0; b < 7; ++b) {
                    ulonglong2 hp = h9[b];
                    fma2(aIF[b], hp.x, w0.x); fma2(aGO[b], hp.x, w0.y);
                    fma2(aIF[b], hp.y, w1.x); fma2(aGO[b], hp.y, w1.y);
                }
            }
            asm volatile("bar.sync 1, 256;" ::: "memory");  // wait x~
            // Wih . x~
            #pragma unroll 2
            for (int np = 0; np < 32; ++np) {
                ulonglong2 w0 = WqI[(size_t)(2 * np) * 128];
                ulonglong2 w1 = WqI[(size_t)(2 * np + 1) * 128];
                const ull* x9 = xw + np * 18;
                #pragma unroll
                for (int b = 0; b < 7; ++b) {
                    ulonglong2 xp = *(const ulonglong2*)(x9 + b * 2);
                    fma2(aIF[b], xp.x, w0.x); fma2(aGO[b], xp.x, w0.y);
                    fma2(aIF[b], xp.y, w1.x); fma2(aGO[b], xp.y, w1.y);
                }
            }
            // pointwise LSTM update
            #pragma unroll
            for (int b = 0; b < 7; ++b) {
                float2 rIF = up2(aIF[b]), rGO = up2(aGO[b]);
                float iv = sigmoid_f(rIF.x);
                float fv = sigmoid_f(rIF.y);
                float gv = tanhf(rGO.x);
                float ov = sigmoid_f(rGO.y);
                float c2 = fv * cr[b] + iv * gv;
                cr[b] = c2;
                float hn = ov * tanhf(c2);
                hw[(qh + b) * 2 + qo] = pk2(hn, hn);
                hw[(qc + b) * 2 + qo] = pk2(c2, c2);
                if (b < cnt)
                    out[((size_t)(b0 + b) * TT + t) * HH + q] = hn;
            }
            asm volatile("bar.sync 2, 256;" ::: "memory");  // h ready
        }
    }
}

// ---------------- launch --------------------------------------------------
extern "C" void kernel_launch(void* const* d_in, const int* in_sizes, int n_in,
                              void* d_out, int out_size) {
    const float* X       = (const float*)d_in[0];
    const float* W_attn1 = (const float*)d_in[1];
    const float* b_attn1 = (const float*)d_in[2];
    const float* w_attn2 = (const float*)d_in[3];
    const float* b_attn2 = (const float*)d_in[4];
    const float* W_ih    = (const float*)d_in[5];
    const float* W_hh    = (const float*)d_in[6];
    const float* b_ih    = (const float*)d_in[7];
    const float* b_hh    = (const float*)d_in[8];
    float* out = (float*)d_out;

    cudaFuncSetAttribute(rnn_kernel, cudaFuncAttributeMaxDynamicSharedMemorySize,
                         SM_BYTES);

    prep_kernel<<<64, 256>>>(W_attn1, W_ih, W_hh, b_ih, b_hh);
    prex_kernel<<<BB, 256>>>(X, b_attn1);
    dummy_kernel<<<1, 32>>>();   // aligns ncu -s 5 -c 1 onto rnn_kernel
    rnn_kernel<<<GRID, THR, SM_BYTES>>>(X, w_attn2, b_attn2, out);
}